// round 4
// baseline (speedup 1.0000x reference)
#include <cuda_runtime.h>
#include <math.h>

#define EPS 1e-8f
#define DIM 256
#define VDIM 64  // DIM/4 float4s per row
#define NBLOCKS 592
#define NTHREADS 512

// Per-block best keys (written unconditionally -> no init kernel needed)
__device__ unsigned long long g_block_best[NBLOCKS];
__device__ unsigned g_done = 0;   // self-resetting arrival counter

__device__ __forceinline__ unsigned long long pack_key(float sim, unsigned row) {
    unsigned u = __float_as_uint(sim);
    u = (u & 0x80000000u) ? ~u : (u | 0x80000000u);  // order-preserving map
    return ((unsigned long long)u << 32) | (0xFFFFFFFFu - row);
}

// ---------------------------------------------------------------------------
// Fused kernel: warp-per-row similarity + packed argmax (4 rows/iter),
// last-arriving block reduces per-block keys, applies query norm, writes out.
// Raw (unnormalized) query in the mainloop: argmax invariant under the
// positive scale 1/(||q||+eps).
// ---------------------------------------------------------------------------
__global__ void __launch_bounds__(NTHREADS, 2)
sim_argmax_kernel(const float4* __restrict__ emb,
                  const float4* __restrict__ q,
                  int n_rows,
                  float* __restrict__ out) {
    __shared__ float4 qs[VDIM];
    if (threadIdx.x < VDIM) qs[threadIdx.x] = q[threadIdx.x];
    __syncthreads();

    const int lane  = threadIdx.x & 31;
    const int warp  = (blockIdx.x * blockDim.x + threadIdx.x) >> 5;
    const int nwarp = (gridDim.x * blockDim.x) >> 5;

    const float4 qa = qs[lane];
    const float4 qb = qs[lane + 32];

    unsigned long long best = 0ULL;

    for (int base = warp; base < n_rows; base += 4 * nwarp) {
        int r0 = base;
        int r1 = base + nwarp;
        int r2 = base + 2 * nwarp;
        int r3 = base + 3 * nwarp;
        bool v1 = (r1 < n_rows), v2 = (r2 < n_rows), v3 = (r3 < n_rows);
        int c1 = v1 ? r1 : r0, c2 = v2 ? r2 : r0, c3 = v3 ? r3 : r0;

        const float4* p0 = emb + (size_t)r0 * VDIM;
        const float4* p1 = emb + (size_t)c1 * VDIM;
        const float4* p2 = emb + (size_t)c2 * VDIM;
        const float4* p3 = emb + (size_t)c3 * VDIM;

        // Front-batched: 8 outstanding LDG.128 per lane
        float4 a0 = __ldcs(p0 + lane);
        float4 b0 = __ldcs(p0 + lane + 32);
        float4 a1 = __ldcs(p1 + lane);
        float4 b1 = __ldcs(p1 + lane + 32);
        float4 a2 = __ldcs(p2 + lane);
        float4 b2 = __ldcs(p2 + lane + 32);
        float4 a3 = __ldcs(p3 + lane);
        float4 b3 = __ldcs(p3 + lane + 32);

        float d0 = a0.x*qa.x + a0.y*qa.y + a0.z*qa.z + a0.w*qa.w
                 + b0.x*qb.x + b0.y*qb.y + b0.z*qb.z + b0.w*qb.w;
        float s0 = a0.x*a0.x + a0.y*a0.y + a0.z*a0.z + a0.w*a0.w
                 + b0.x*b0.x + b0.y*b0.y + b0.z*b0.z + b0.w*b0.w;
        float d1 = a1.x*qa.x + a1.y*qa.y + a1.z*qa.z + a1.w*qa.w
                 + b1.x*qb.x + b1.y*qb.y + b1.z*qb.z + b1.w*qb.w;
        float s1 = a1.x*a1.x + a1.y*a1.y + a1.z*a1.z + a1.w*a1.w
                 + b1.x*b1.x + b1.y*b1.y + b1.z*b1.z + b1.w*b1.w;
        float d2 = a2.x*qa.x + a2.y*qa.y + a2.z*qa.z + a2.w*qa.w
                 + b2.x*qb.x + b2.y*qb.y + b2.z*qb.z + b2.w*qb.w;
        float s2 = a2.x*a2.x + a2.y*a2.y + a2.z*a2.z + a2.w*a2.w
                 + b2.x*b2.x + b2.y*b2.y + b2.z*b2.z + b2.w*b2.w;
        float d3 = a3.x*qa.x + a3.y*qa.y + a3.z*qa.z + a3.w*qa.w
                 + b3.x*qb.x + b3.y*qb.y + b3.z*qb.z + b3.w*qb.w;
        float s3 = a3.x*a3.x + a3.y*a3.y + a3.z*a3.z + a3.w*a3.w
                 + b3.x*b3.x + b3.y*b3.y + b3.z*b3.z + b3.w*b3.w;

        #pragma unroll
        for (int off = 16; off > 0; off >>= 1) {
            d0 += __shfl_down_sync(0xFFFFFFFFu, d0, off);
            s0 += __shfl_down_sync(0xFFFFFFFFu, s0, off);
            d1 += __shfl_down_sync(0xFFFFFFFFu, d1, off);
            s1 += __shfl_down_sync(0xFFFFFFFFu, s1, off);
            d2 += __shfl_down_sync(0xFFFFFFFFu, d2, off);
            s2 += __shfl_down_sync(0xFFFFFFFFu, s2, off);
            d3 += __shfl_down_sync(0xFFFFFFFFu, d3, off);
            s3 += __shfl_down_sync(0xFFFFFFFFu, s3, off);
        }

        if (lane == 0) {
            unsigned long long k;
            k = pack_key(d0 / (sqrtf(s0) + EPS), (unsigned)r0);
            if (k > best) best = k;
            if (v1) {
                k = pack_key(d1 / (sqrtf(s1) + EPS), (unsigned)r1);
                if (k > best) best = k;
            }
            if (v2) {
                k = pack_key(d2 / (sqrtf(s2) + EPS), (unsigned)r2);
                if (k > best) best = k;
            }
            if (v3) {
                k = pack_key(d3 / (sqrtf(s3) + EPS), (unsigned)r3);
                if (k > best) best = k;
            }
        }
    }

    // ---- block reduce (lane 0 of each warp holds its best) ----
    __shared__ unsigned long long sb[NTHREADS / 32];
    __shared__ bool s_is_last;
    int wib = threadIdx.x >> 5;
    if (lane == 0) sb[wib] = best;
    __syncthreads();
    if (threadIdx.x == 0) {
        unsigned long long m = sb[0];
        #pragma unroll
        for (int i = 1; i < NTHREADS / 32; i++) if (sb[i] > m) m = sb[i];
        g_block_best[blockIdx.x] = m;   // unconditional write: no init needed
        __threadfence();
        unsigned old = atomicAdd(&g_done, 1u);
        s_is_last = (old == (unsigned)(gridDim.x - 1));
    }
    __syncthreads();

    // ---- last-arriving block: global reduce + query norm + output ----
    if (s_is_last) {
        __shared__ float red[256];
        __shared__ unsigned long long kred[256];
        int t = threadIdx.x;

        if (t < 256) {
            float v = ((const float*)q)[t];
            red[t] = v * v;

            unsigned long long m = 0ULL;
            for (int i = t; i < NBLOCKS; i += 256) {
                unsigned long long k = g_block_best[i];
                if (k > m) m = k;
            }
            kred[t] = m;
        }
        __syncthreads();

        for (int s = 128; s > 0; s >>= 1) {
            if (t < s) {
                red[t] += red[t + s];
                if (kred[t + s] > kred[t]) kred[t] = kred[t + s];
            }
            __syncthreads();
        }

        if (t == 0) {
            float qscale = 1.0f / (sqrtf(red[0]) + EPS);
            unsigned long long k = kred[0];
            unsigned idx = 0xFFFFFFFFu - (unsigned)(k & 0xFFFFFFFFu);
            unsigned u = (unsigned)(k >> 32);
            unsigned bits = (u & 0x80000000u) ? (u ^ 0x80000000u) : ~u;
            out[0] = (float)idx;
            out[1] = __uint_as_float(bits) * qscale;
            g_done = 0;   // self-reset for the next graph replay
        }
    }
}

extern "C" void kernel_launch(void* const* d_in, const int* in_sizes, int n_in,
                              void* d_out, int out_size) {
    const float* q   = (const float*)d_in[0];
    const float* emb = (const float*)d_in[1];
    int n_rows = in_sizes[1] / DIM;

    sim_argmax_kernel<<<NBLOCKS, NTHREADS>>>((const float4*)emb,
                                             (const float4*)q, n_rows,
                                             (float*)d_out);
}

// round 5
// speedup vs baseline: 1.0080x; 1.0080x over previous
#include <cuda_runtime.h>
#include <math.h>

#define EPS 1e-8f
#define DIM 256
#define VDIM 64   // DIM/4 float4s per row
#define NBLOCKS 296   // 148 SMs * 2 resident blocks: single persistent wave
#define NTHREADS 512

// Per-block best keys (written unconditionally -> no init kernel needed)
__device__ unsigned long long g_block_best[NBLOCKS];

__device__ __forceinline__ unsigned long long pack_key(float sim, unsigned row) {
    unsigned u = __float_as_uint(sim);
    u = (u & 0x80000000u) ? ~u : (u | 0x80000000u);  // order-preserving map
    return ((unsigned long long)u << 32) | (0xFFFFFFFFu - row);
}

// ---------------------------------------------------------------------------
// Kernel A: warp-per-row similarity + packed argmax, 4 rows per iteration.
// Persistent single-wave grid. Raw (unnormalized) query: argmax invariant
// under the positive scale 1/(||q||+eps); decode applies it to the score.
// ---------------------------------------------------------------------------
__global__ void __launch_bounds__(NTHREADS, 2)
sim_argmax_kernel(const float4* __restrict__ emb,
                  const float4* __restrict__ q,
                  int n_rows) {
    __shared__ float4 qs[VDIM];
    if (threadIdx.x < VDIM) qs[threadIdx.x] = q[threadIdx.x];
    __syncthreads();

    const int lane  = threadIdx.x & 31;
    const int warp  = (blockIdx.x * blockDim.x + threadIdx.x) >> 5;
    const int nwarp = (gridDim.x * blockDim.x) >> 5;

    const float4 qa = qs[lane];
    const float4 qb = qs[lane + 32];

    unsigned long long best = 0ULL;

    for (int base = warp; base < n_rows; base += 4 * nwarp) {
        int r0 = base;
        int r1 = base + nwarp;
        int r2 = base + 2 * nwarp;
        int r3 = base + 3 * nwarp;
        bool v1 = (r1 < n_rows), v2 = (r2 < n_rows), v3 = (r3 < n_rows);
        int c1 = v1 ? r1 : r0, c2 = v2 ? r2 : r0, c3 = v3 ? r3 : r0;

        const float4* p0 = emb + (size_t)r0 * VDIM;
        const float4* p1 = emb + (size_t)c1 * VDIM;
        const float4* p2 = emb + (size_t)c2 * VDIM;
        const float4* p3 = emb + (size_t)c3 * VDIM;

        // Front-batched: 8 outstanding LDG.128 per lane
        float4 a0 = __ldcs(p0 + lane);
        float4 b0 = __ldcs(p0 + lane + 32);
        float4 a1 = __ldcs(p1 + lane);
        float4 b1 = __ldcs(p1 + lane + 32);
        float4 a2 = __ldcs(p2 + lane);
        float4 b2 = __ldcs(p2 + lane + 32);
        float4 a3 = __ldcs(p3 + lane);
        float4 b3 = __ldcs(p3 + lane + 32);

        float d0 = a0.x*qa.x + a0.y*qa.y + a0.z*qa.z + a0.w*qa.w
                 + b0.x*qb.x + b0.y*qb.y + b0.z*qb.z + b0.w*qb.w;
        float s0 = a0.x*a0.x + a0.y*a0.y + a0.z*a0.z + a0.w*a0.w
                 + b0.x*b0.x + b0.y*b0.y + b0.z*b0.z + b0.w*b0.w;
        float d1 = a1.x*qa.x + a1.y*qa.y + a1.z*qa.z + a1.w*qa.w
                 + b1.x*qb.x + b1.y*qb.y + b1.z*qb.z + b1.w*qb.w;
        float s1 = a1.x*a1.x + a1.y*a1.y + a1.z*a1.z + a1.w*a1.w
                 + b1.x*b1.x + b1.y*b1.y + b1.z*b1.z + b1.w*b1.w;
        float d2 = a2.x*qa.x + a2.y*qa.y + a2.z*qa.z + a2.w*qa.w
                 + b2.x*qb.x + b2.y*qb.y + b2.z*qb.z + b2.w*qb.w;
        float s2 = a2.x*a2.x + a2.y*a2.y + a2.z*a2.z + a2.w*a2.w
                 + b2.x*b2.x + b2.y*b2.y + b2.z*b2.z + b2.w*b2.w;
        float d3 = a3.x*qa.x + a3.y*qa.y + a3.z*qa.z + a3.w*qa.w
                 + b3.x*qb.x + b3.y*qb.y + b3.z*qb.z + b3.w*qb.w;
        float s3 = a3.x*a3.x + a3.y*a3.y + a3.z*a3.z + a3.w*a3.w
                 + b3.x*b3.x + b3.y*b3.y + b3.z*b3.z + b3.w*b3.w;

        #pragma unroll
        for (int off = 16; off > 0; off >>= 1) {
            d0 += __shfl_down_sync(0xFFFFFFFFu, d0, off);
            s0 += __shfl_down_sync(0xFFFFFFFFu, s0, off);
            d1 += __shfl_down_sync(0xFFFFFFFFu, d1, off);
            s1 += __shfl_down_sync(0xFFFFFFFFu, s1, off);
            d2 += __shfl_down_sync(0xFFFFFFFFu, d2, off);
            s2 += __shfl_down_sync(0xFFFFFFFFu, s2, off);
            d3 += __shfl_down_sync(0xFFFFFFFFu, d3, off);
            s3 += __shfl_down_sync(0xFFFFFFFFu, s3, off);
        }

        if (lane == 0) {
            unsigned long long k;
            k = pack_key(d0 / (sqrtf(s0) + EPS), (unsigned)r0);
            if (k > best) best = k;
            if (v1) {
                k = pack_key(d1 / (sqrtf(s1) + EPS), (unsigned)r1);
                if (k > best) best = k;
            }
            if (v2) {
                k = pack_key(d2 / (sqrtf(s2) + EPS), (unsigned)r2);
                if (k > best) best = k;
            }
            if (v3) {
                k = pack_key(d3 / (sqrtf(s3) + EPS), (unsigned)r3);
                if (k > best) best = k;
            }
        }
    }

    // block reduce (lane 0 of each warp holds its best)
    __shared__ unsigned long long sb[NTHREADS / 32];
    int wib = threadIdx.x >> 5;
    if (lane == 0) sb[wib] = best;
    __syncthreads();
    if (threadIdx.x == 0) {
        unsigned long long m = sb[0];
        #pragma unroll
        for (int i = 1; i < NTHREADS / 32; i++) if (sb[i] > m) m = sb[i];
        g_block_best[blockIdx.x] = m;   // unconditional write: no init needed
    }
}

// ---------------------------------------------------------------------------
// Kernel B: reduce per-block keys + query norm -> [best_idx, best_score]
// ---------------------------------------------------------------------------
__global__ void decode_kernel(const float* __restrict__ q, float* __restrict__ out) {
    __shared__ float red[256];
    __shared__ unsigned long long kred[256];
    int t = threadIdx.x;

    float v = q[t];
    red[t] = v * v;

    unsigned long long m = 0ULL;
    for (int i = t; i < NBLOCKS; i += 256) {
        unsigned long long k = g_block_best[i];
        if (k > m) m = k;
    }
    kred[t] = m;
    __syncthreads();

    for (int s = 128; s > 0; s >>= 1) {
        if (t < s) {
            red[t] += red[t + s];
            if (kred[t + s] > kred[t]) kred[t] = kred[t + s];
        }
        __syncthreads();
    }

    if (t == 0) {
        float qscale = 1.0f / (sqrtf(red[0]) + EPS);
        unsigned long long k = kred[0];
        unsigned idx = 0xFFFFFFFFu - (unsigned)(k & 0xFFFFFFFFu);
        unsigned u = (unsigned)(k >> 32);
        unsigned bits = (u & 0x80000000u) ? (u ^ 0x80000000u) : ~u;
        out[0] = (float)idx;
        out[1] = __uint_as_float(bits) * qscale;
    }
}

extern "C" void kernel_launch(void* const* d_in, const int* in_sizes, int n_in,
                              void* d_out, int out_size) {
    const float* q   = (const float*)d_in[0];
    const float* emb = (const float*)d_in[1];
    int n_rows = in_sizes[1] / DIM;

    sim_argmax_kernel<<<NBLOCKS, NTHREADS>>>((const float4*)emb,
                                             (const float4*)q, n_rows);
    decode_kernel<<<1, 256>>>(q, (float*)d_out);
}

// round 6
// speedup vs baseline: 1.0108x; 1.0028x over previous
#include <cuda_runtime.h>
#include <math.h>

#define EPS 1e-8f
#define DIM 256
#define VDIM 64   // DIM/4 float4s per row
#define NBLOCKS 592   // R3-proven best grid
#define NTHREADS 512

// Per-block best keys + tail slots (written unconditionally -> no init kernel)
__device__ unsigned long long g_block_best[NBLOCKS];
__device__ unsigned long long g_tail_best[4];

__device__ __forceinline__ unsigned long long pack_key(float sim, unsigned row) {
    unsigned u = __float_as_uint(sim);
    u = (u & 0x80000000u) ? ~u : (u | 0x80000000u);  // order-preserving map
    return ((unsigned long long)u << 32) | (0xFFFFFFFFu - row);
}

// ---------------------------------------------------------------------------
// Kernel A: 16-lane-per-row similarity + packed argmax, 4 rows/warp/iter.
// Raw (unnormalized) query: argmax invariant under positive scale
// 1/(||q||+eps); decode kernel applies it to the winning score only.
// ---------------------------------------------------------------------------
__global__ void __launch_bounds__(NTHREADS, 2)
sim_argmax_kernel(const float4* __restrict__ emb,
                  const float4* __restrict__ q,
                  int n_rows) {
    __shared__ float4 qs[VDIM];
    if (threadIdx.x < VDIM) qs[threadIdx.x] = q[threadIdx.x];
    __syncthreads();

    const int lane  = threadIdx.x & 31;
    const int g     = lane >> 4;        // row group within warp (0 or 1)
    const int j     = lane & 15;        // lane within group
    const int warp  = (blockIdx.x * blockDim.x + threadIdx.x) >> 5;
    const int nwarp = (gridDim.x * blockDim.x) >> 5;

    // Each lane's quarter of the query (float4 indices j, j+16, j+32, j+48)
    const float4 q0 = qs[j];
    const float4 q1 = qs[j + 16];
    const float4 q2 = qs[j + 32];
    const float4 q3 = qs[j + 48];

    const int n4 = n_rows & ~3;
    unsigned long long best = 0ULL;

    for (int base = warp * 4; base < n4; base += 4 * nwarp) {
        const int rA = base + g;
        const int rB = base + 2 + g;
        const float4* pA = emb + (size_t)rA * VDIM;
        const float4* pB = emb + (size_t)rB * VDIM;

        // Front-batched: 8 outstanding LDG.128 per lane
        float4 a0 = __ldcs(pA + j);
        float4 a1 = __ldcs(pA + j + 16);
        float4 a2 = __ldcs(pA + j + 32);
        float4 a3 = __ldcs(pA + j + 48);
        float4 b0 = __ldcs(pB + j);
        float4 b1 = __ldcs(pB + j + 16);
        float4 b2 = __ldcs(pB + j + 32);
        float4 b3 = __ldcs(pB + j + 48);

        float dA = a0.x*q0.x + a0.y*q0.y + a0.z*q0.z + a0.w*q0.w
                 + a1.x*q1.x + a1.y*q1.y + a1.z*q1.z + a1.w*q1.w
                 + a2.x*q2.x + a2.y*q2.y + a2.z*q2.z + a2.w*q2.w
                 + a3.x*q3.x + a3.y*q3.y + a3.z*q3.z + a3.w*q3.w;
        float sA = a0.x*a0.x + a0.y*a0.y + a0.z*a0.z + a0.w*a0.w
                 + a1.x*a1.x + a1.y*a1.y + a1.z*a1.z + a1.w*a1.w
                 + a2.x*a2.x + a2.y*a2.y + a2.z*a2.z + a2.w*a2.w
                 + a3.x*a3.x + a3.y*a3.y + a3.z*a3.z + a3.w*a3.w;
        float dB = b0.x*q0.x + b0.y*q0.y + b0.z*q0.z + b0.w*q0.w
                 + b1.x*q1.x + b1.y*q1.y + b1.z*q1.z + b1.w*q1.w
                 + b2.x*q2.x + b2.y*q2.y + b2.z*q2.z + b2.w*q2.w
                 + b3.x*q3.x + b3.y*q3.y + b3.z*q3.z + b3.w*q3.w;
        float sB = b0.x*b0.x + b0.y*b0.y + b0.z*b0.z + b0.w*b0.w
                 + b1.x*b1.x + b1.y*b1.y + b1.z*b1.z + b1.w*b1.w
                 + b2.x*b2.x + b2.y*b2.y + b2.z*b2.z + b2.w*b2.w
                 + b3.x*b3.x + b3.y*b3.y + b3.z*b3.z + b3.w*b3.w;

        // Width-16 reduce: 4 independent chains x 4 levels = 16 shuffles
        #pragma unroll
        for (int off = 8; off > 0; off >>= 1) {
            dA += __shfl_down_sync(0xFFFFFFFFu, dA, off, 16);
            sA += __shfl_down_sync(0xFFFFFFFFu, sA, off, 16);
            dB += __shfl_down_sync(0xFFFFFFFFu, dB, off, 16);
            sB += __shfl_down_sync(0xFFFFFFFFu, sB, off, 16);
        }

        if (j == 0) {   // lanes 0 and 16
            unsigned long long k;
            k = pack_key(dA / (sqrtf(sA) + EPS), (unsigned)rA);
            if (k > best) best = k;
            k = pack_key(dB / (sqrtf(sB) + EPS), (unsigned)rB);
            if (k > best) best = k;
        }
    }

    // Tail rows (n_rows % 4): handled scalar by block 0, threads 0..3.
    // Slots written unconditionally so no init is needed.
    if (blockIdx.x == 0 && threadIdx.x < 4) {
        int r = n4 + threadIdx.x;
        unsigned long long k = 0ULL;
        if (r < n_rows) {
            const float4* p = emb + (size_t)r * VDIM;
            float d = 0.f, s = 0.f;
            for (int i = 0; i < VDIM; i++) {
                float4 a = p[i];
                float4 qq = qs[i];
                d += a.x*qq.x + a.y*qq.y + a.z*qq.z + a.w*qq.w;
                s += a.x*a.x + a.y*a.y + a.z*a.z + a.w*a.w;
            }
            k = pack_key(d / (sqrtf(s) + EPS), (unsigned)r);
        }
        g_tail_best[threadIdx.x] = k;
    }

    // warp-wide max of per-lane bests (only lanes 0,16 carry nonzero)
    #pragma unroll
    for (int off = 16; off > 0; off >>= 1) {
        unsigned long long o = __shfl_down_sync(0xFFFFFFFFu, best, off);
        if (o > best) best = o;
    }

    __shared__ unsigned long long sb[NTHREADS / 32];
    int wib = threadIdx.x >> 5;
    if (lane == 0) sb[wib] = best;
    __syncthreads();
    if (threadIdx.x == 0) {
        unsigned long long m = sb[0];
        #pragma unroll
        for (int i = 1; i < NTHREADS / 32; i++) if (sb[i] > m) m = sb[i];
        g_block_best[blockIdx.x] = m;   // unconditional write: no init needed
    }
}

// ---------------------------------------------------------------------------
// Kernel B: reduce per-block keys + tail + query norm -> [best_idx, best_score]
// ---------------------------------------------------------------------------
__global__ void decode_kernel(const float* __restrict__ q, float* __restrict__ out) {
    __shared__ float red[256];
    __shared__ unsigned long long kred[256];
    int t = threadIdx.x;

    float v = q[t];
    red[t] = v * v;

    unsigned long long m = 0ULL;
    for (int i = t; i < NBLOCKS; i += 256) {
        unsigned long long k = g_block_best[i];
        if (k > m) m = k;
    }
    if (t < 4) {
        unsigned long long k = g_tail_best[t];
        if (k > m) m = k;
    }
    kred[t] = m;
    __syncthreads();

    for (int s = 128; s > 0; s >>= 1) {
        if (t < s) {
            red[t] += red[t + s];
            if (kred[t + s] > kred[t]) kred[t] = kred[t + s];
        }
        __syncthreads();
    }

    if (t == 0) {
        float qscale = 1.0f / (sqrtf(red[0]) + EPS);
        unsigned long long k = kred[0];
        unsigned idx = 0xFFFFFFFFu - (unsigned)(k & 0xFFFFFFFFu);
        unsigned u = (unsigned)(k >> 32);
        unsigned bits = (u & 0x80000000u) ? (u ^ 0x80000000u) : ~u;
        out[0] = (float)idx;
        out[1] = __uint_as_float(bits) * qscale;
    }
}

extern "C" void kernel_launch(void* const* d_in, const int* in_sizes, int n_in,
                              void* d_out, int out_size) {
    const float* q   = (const float*)d_in[0];
    const float* emb = (const float*)d_in[1];
    int n_rows = in_sizes[1] / DIM;

    sim_argmax_kernel<<<NBLOCKS, NTHREADS>>>((const float4*)emb,
                                             (const float4*)q, n_rows);
    decode_kernel<<<1, 256>>>(q, (float*)d_out);
}